// round 14
// baseline (speedup 1.0000x reference)
#include <cuda_runtime.h>
#include <math.h>
#include <stdint.h>

#define NROW      4096
#define NT        512
#define RPT       8
#define NCELL     5
#define POWK      20     // power-iteration steps (bulk leak 0.41^20 ~ 1.7e-8)
#define NEUM1     14     // Richardson steps, first pass
#define NEUM2     10     // Richardson steps, later passes
#define MAX_OUTER 3

// smem doubles: xd[4097] wdm[4096] bhdm[4096] scrd[40]; floats: pf[4097] sf[4097] scrf[32]
#define SM_BYTES ((4097 + 4096 + 4096 + 40) * 8 + (4097 + 4097 + 32) * 4)

__device__ double g_IM[75];
__device__ int    g_cnt = 0;

__device__ __forceinline__ double warp_red_d(double v) {
#pragma unroll
    for (int o = 16; o; o >>= 1) v += __shfl_down_sync(0xFFFFFFFFu, v, o);
    return v;
}
__device__ __forceinline__ double blk_red_d(double v, double* scr, int tid) {
    int lane = tid & 31, wid = tid >> 5;
    v = warp_red_d(v);
    if (lane == 0) scr[wid] = v;
    __syncthreads();
    if (wid == 0) {
        double u = (lane < 16) ? scr[lane] : 0.0;
#pragma unroll
        for (int o = 8; o; o >>= 1) u += __shfl_down_sync(0xFFFFFFFFu, u, o);
        if (lane == 0) scr[32] = u;
    }
    __syncthreads();
    return scr[32];
}
__device__ __forceinline__ void bredd5(double v[5], double* scr, int tid) {
    int lane = tid & 31, wid = tid >> 5;
#pragma unroll
    for (int k = 0; k < 5; k++) v[k] = warp_red_d(v[k]);
    if (lane == 0) {
#pragma unroll
        for (int k = 0; k < 5; k++) scr[k * 16 + wid] = v[k];
    }
    __syncthreads();
    if (wid < 5) {
        double u = (lane < 16) ? scr[wid * 16 + lane] : 0.0;
#pragma unroll
        for (int o = 8; o; o >>= 1) u += __shfl_down_sync(0xFFFFFFFFu, u, o);
        if (lane == 0) scr[80 + wid] = u;
    }
    __syncthreads();
#pragma unroll
    for (int k = 0; k < 5; k++) v[k] = scr[80 + k];
}
// single-barrier fp32 block reduction (16 warps)
__device__ __forceinline__ float bred1(float v, float* scr, int tid) {
    const int lane = tid & 31, wid = tid >> 5;
#pragma unroll
    for (int o = 16; o; o >>= 1) v += __shfl_xor_sync(0xFFFFFFFFu, v, o);
    if (lane == 0) scr[wid] = v;
    __syncthreads();
    float u = scr[lane & 15];
#pragma unroll
    for (int o = 8; o; o >>= 1) u += __shfl_xor_sync(0xFFFFFFFFu, u, o);
    return u;
}

#define GATHF(arr, q0, q1, q2)                                                \
    ( *(const float*)((const char*)(arr) + ((q0) & 0xFFFFu))                  \
    + *(const float*)((const char*)(arr) + ((q0) >> 16))                      \
    + *(const float*)((const char*)(arr) + ((q1) & 0xFFFFu))                  \
    + *(const float*)((const char*)(arr) + ((q1) >> 16))                      \
    + *(const float*)((const char*)(arr) + ((q2) & 0xFFFFu))                  \
    + *(const float*)((const char*)(arr) + ((q2) >> 16)) )
#define GATHD(arr, q0, q1, q2)                                                \
    ( *(const double*)((const char*)(arr) + (((q0) & 0xFFFFu) << 1))          \
    + *(const double*)((const char*)(arr) + (((q0) >> 16)     << 1))          \
    + *(const double*)((const char*)(arr) + (((q1) & 0xFFFFu) << 1))          \
    + *(const double*)((const char*)(arr) + (((q1) >> 16)     << 1))          \
    + *(const double*)((const char*)(arr) + (((q2) & 0xFFFFu) << 1))          \
    + *(const double*)((const char*)(arr) + (((q2) >> 16)     << 1)) )

__global__ __launch_bounds__(NT, 1)
void solve_kernel(const float* __restrict__ th1,
                  const float* __restrict__ th2,
                  const float* __restrict__ th3,
                  const float* __restrict__ cd,
                  const float* __restrict__ Iexp,
                  const int*   __restrict__ nbr,
                  float*       __restrict__ out)
{
    extern __shared__ double sm[];
    double* xd   = sm;                 // 4097 (pad slot 4096 == 0)
    double* wdm  = sm + 4097;          // 4096 fp64 Jacobi weight
    double* bhdm = sm + 8193;          // 4096 fp64 hatted RHS
    double* scrd = sm + 12289;         // 40
    float*  fb   = (float*)(sm + 12329);
    float* pf   = fb;                  // 4097 (pad 0) — buffer A
    float* sf   = fb + 4097;           // 4097 (pad 0) — buffer B
    float* scrf = fb + 8194;           // 32
    __shared__ int s_last;

    const int tid = threadIdx.x;
    const int sys = blockIdx.x;
    const float* th = (sys == 0) ? th1 : ((sys == 1) ? th2 : th3);

    const double L_C     = 8.45e-05;
    const double L_RATIO = 1.0 / sqrt(3.0);
    const double AREA    = sqrt(3.0) * 0.5 * L_C * L_C;
    const double A_SCALE = 1.0e11;
    const double B_SCALE = 1.0e23;

    const double D   = (double)th[0];
    const double lam = (double)th[1];
    const double K   = (double)th[7];
    double rho_p[NCELL], rec[NCELL], recK[NCELL];
#pragma unroll
    for (int c = 0; c < NCELL; c++) {
        rho_p[c] = (double)th[2 + c];
        rec[c]   = (double)th[8 + c];
        recK[c]  = rec[c] * K;
    }
    const double Dp = D * L_RATIO;

    // register state
    uint32_t pk[RPT][3];               // packed byte offsets (idx*4), pad = 4096*4
    float wf[RPT];
    float rg[RPT], dx[RPT], vr[RPT], ug[RPT];

    // ---- setup ----
    double bb_part = 0.0;
#pragma unroll
    for (int t = 0; t < RPT; t++) {
        const int i = tid + t * NT;
        int nb[6];
#pragma unroll
        for (int j = 0; j < 6; j++) nb[j] = nbr[i * 6 + j];
#pragma unroll
        for (int j = 1; j < 6; j++)
#pragma unroll
            for (int l = 0; l < 6; l++)
                if (l < j && nb[j] == nb[l]) nb[j] = NROW;   // dup -> pad slot
        pk[t][0] = ((uint32_t)nb[0] * 4u) | (((uint32_t)nb[1] * 4u) << 16);
        pk[t][1] = ((uint32_t)nb[2] * 4u) | (((uint32_t)nb[3] * 4u) << 16);
        pk[t][2] = ((uint32_t)nb[4] * 4u) | (((uint32_t)nb[5] * 4u) << 16);

        double drec = 0.0, drho = 0.0;
#pragma unroll
        for (int c = 0; c < NCELL; c++) {
            const double f = (double)cd[i * NCELL + c];
            drec += f * recK[c];
            drho += f * rho_p[c];
        }
        const double diag = 6.0 * Dp + AREA * (lam + drec);
        const double wdv  = Dp / diag;
        const double bh   = AREA * drho * B_SCALE / (A_SCALE * diag);
        wdm[i]  = wdv;
        bhdm[i] = bh;
        wf[t]   = (float)wdv;
        rg[t]   = (float)bh;
        dx[t]   = 0.0f;
        vr[t]   = 1.0f;                 // power iteration start: e
        xd[i]   = 0.0;
        bb_part += bh * bh;
    }
    if (tid == 0) { pf[NROW] = 0.0f; sf[NROW] = 0.0f; xd[NROW] = 0.0; }
    __syncthreads();

    const double bb   = blk_red_d(bb_part, scrd, tid);
    const double tolo = bb * 9e-10;    // outer relres 3e-5

    // ---- power iteration: v = N^POWK e (1 barrier/step) ----
#pragma unroll 1
    for (int k = 0; k < POWK; k++) {
        float* buf = (k & 1) ? sf : pf;
#pragma unroll
        for (int t = 0; t < RPT; t++) buf[tid + t * NT] = vr[t];
        __syncthreads();
#pragma unroll
        for (int t = 0; t < RPT; t++)
            vr[t] = wf[t] * GATHF(buf, pk[t][0], pk[t][1], pk[t][2]);
    }

    // ---- u = (I - N) v in fp64 (cancellation-critical) ----
#pragma unroll
    for (int t = 0; t < RPT; t++) xd[tid + t * NT] = (double)vr[t];
    __syncthreads();
    float inv_uu;
    {
        double uu_p = 0.0;
#pragma unroll
        for (int t = 0; t < RPT; t++) {
            const int i = tid + t * NT;
            const double sum = GATHD(xd, pk[t][0], pk[t][1], pk[t][2]);
            const double ud  = (double)vr[t] - wdm[i] * sum;
            ug[t] = (float)ud;
            uu_p += ud * ud;
        }
        const double uu = blk_red_d(uu_p, scrd, tid);   // barriers end xd reads
        inv_uu = (uu > 0.0) ? (float)(1.0 / uu) : 0.0f;
    }
#pragma unroll
    for (int t = 0; t < RPT; t++) xd[tid + t * NT] = 0.0;   // own slots only

    double rn2d = bb;

#pragma unroll 1
    for (int outer = 0; outer < MAX_OUTER && rn2d > tolo; outer++) {
        // -- deflate Perron mode: c = <u,r>/<u,u> ; fp64 C folded at pass end --
        float up = 0.0f;
#pragma unroll
        for (int t = 0; t < RPT; t++) up = fmaf(ug[t], rg[t], up);
        up = bred1(up, scrf, tid);
        const float  c  = up * inv_uu;
        const double Cd = (double)c;
#pragma unroll
        for (int t = 0; t < RPT; t++) rg[t] = fmaf(-c, ug[t], rg[t]);

        // -- Richardson: dx += r ; r = N r  (1 barrier/step) --
        const int nsteps = (outer == 0) ? NEUM1 : NEUM2;
#pragma unroll 1
        for (int k = 0; k < nsteps; k++) {
            float* buf = (k & 1) ? sf : pf;
#pragma unroll
            for (int t = 0; t < RPT; t++) buf[tid + t * NT] = rg[t];
            __syncthreads();
#pragma unroll
            for (int t = 0; t < RPT; t++) {
                const float sum = GATHF(buf, pk[t][0], pk[t][1], pk[t][2]);
                dx[t] += rg[t];
                rg[t] = wf[t] * sum;
            }
        }

        // -- fold (fp64: bulk dx + deflation C·v) ; true fp64 residual --
#pragma unroll
        for (int t = 0; t < RPT; t++) {
            xd[tid + t * NT] += (double)dx[t] + Cd * (double)vr[t];
            dx[t] = 0.0f;
        }
        __syncthreads();
        double rp = 0.0;
#pragma unroll
        for (int t = 0; t < RPT; t++) {
            const int i = tid + t * NT;
            const double sum = GATHD(xd, pk[t][0], pk[t][1], pk[t][2]);
            const double rdi = bhdm[i] - (xd[i] - wdm[i] * sum);
            rg[t] = (float)rdi;
            rp += rdi * rdi;
        }
        rn2d = blk_red_d(rp, scrd, tid);   // also orders state for next pass
    }

    // ---- epilogue (fp64) ----
    double part[NCELL] = {0, 0, 0, 0, 0};
#pragma unroll
    for (int t = 0; t < RPT; t++) {
        const int i = tid + t * NT;
        double num[NCELL], den = 0.0;
#pragma unroll
        for (int c = 0; c < NCELL; c++) {
            num[c] = (double)cd[i * NCELL + c] * rho_p[c];
            den += num[c];
        }
        const double gi = xd[i] / den;
#pragma unroll
        for (int c = 0; c < NCELL; c++) part[c] += gi * num[c];
    }
    bredd5(part, scrd, tid);

    if (tid < 25) {
        const int a = tid / 5, c = tid % 5;
        g_IM[sys * 25 + tid] = K * rec[a] * part[c] / (double)NROW;
        __threadfence();
    }
    __syncthreads();

    // ---- last block computes the loss ----
    if (tid == 0) {
        __threadfence();
        s_last = (atomicAdd(&g_cnt, 1) == 2) ? 1 : 0;
    }
    __syncthreads();
    if (s_last && tid < 32) {
        __threadfence();
        double s_m = 0, s_d = 0, s_mm = 0, s_dd = 0, s_md = 0;
        for (int i = tid; i < 75; i += 32) {
            const double m = *((volatile double*)&g_IM[i]);
            const double d = (double)Iexp[i];
            s_m += m; s_d += d; s_mm += m * m; s_dd += d * d; s_md += m * d;
        }
        s_m  = warp_red_d(s_m);
        s_d  = warp_red_d(s_d);
        s_mm = warp_red_d(s_mm);
        s_dd = warp_red_d(s_dd);
        s_md = warp_red_d(s_md);
        if (tid == 0) {
            const double n  = 75.0;
            const double mm = s_m / n, md = s_d / n;
            const double cov = s_md / n - mm * md;
            const double vm  = s_mm / n - mm * mm;
            const double vd  = s_dd / n - md * md;
            out[0] = (float)(1.0 - cov / (sqrt(vm) * sqrt(vd)));
            atomicExch(&g_cnt, 0);
        }
    }
}

extern "C" void kernel_launch(void* const* d_in, const int* in_sizes, int n_in,
                              void* d_out, int out_size)
{
    const float* th1  = (const float*)d_in[0];
    const float* th2  = (const float*)d_in[1];
    const float* th3  = (const float*)d_in[2];
    const float* cd   = (const float*)d_in[3];
    const float* Iexp = (const float*)d_in[4];
    const int*   nbr  = (const int*)d_in[5];

    cudaFuncSetAttribute(solve_kernel,
                         cudaFuncAttributeMaxDynamicSharedMemorySize, SM_BYTES);

    solve_kernel<<<3, NT, SM_BYTES>>>(th1, th2, th3, cd, Iexp, nbr, (float*)d_out);
}

// round 15
// speedup vs baseline: 1.3902x; 1.3902x over previous
#include <cuda_runtime.h>
#include <math.h>
#include <stdint.h>

#define NROW      4096
#define NT        512
#define RPT       8
#define NCELL     5
#define NEUM1A    14     // Richardson steps before deflation (r -> Perron estimate)
#define NEUM1B    5      // steps after first deflation
#define NEUM2     6      // steps in safety passes
#define MAX_OUTER 3

// smem doubles: xd[4097] vd[4097] wdm[4096] bhdm[4096] scrd[40]
// smem floats:  pf[4097] sf[4097] scrf[32]
#define SM_DBL  (4097 + 4097 + 4096 + 4096 + 40)
#define SM_BYTES (SM_DBL * 8 + (4097 + 4097 + 32) * 4)

__device__ double g_IM[75];
__device__ int    g_cnt = 0;

__device__ __forceinline__ double warp_red_d(double v) {
#pragma unroll
    for (int o = 16; o; o >>= 1) v += __shfl_down_sync(0xFFFFFFFFu, v, o);
    return v;
}
__device__ __forceinline__ double blk_red_d(double v, double* scr, int tid) {
    int lane = tid & 31, wid = tid >> 5;
    v = warp_red_d(v);
    if (lane == 0) scr[wid] = v;
    __syncthreads();
    if (wid == 0) {
        double u = (lane < 16) ? scr[lane] : 0.0;
#pragma unroll
        for (int o = 8; o; o >>= 1) u += __shfl_down_sync(0xFFFFFFFFu, u, o);
        if (lane == 0) scr[32] = u;
    }
    __syncthreads();
    return scr[32];
}
// fused 2-way fp64 block reduction
__device__ __forceinline__ void bredd2(double& a, double& b, double* scr, int tid) {
    int lane = tid & 31, wid = tid >> 5;
    a = warp_red_d(a);
    b = warp_red_d(b);
    if (lane == 0) { scr[wid] = a; scr[16 + wid] = b; }
    __syncthreads();
    if (wid < 2) {
        double u = (lane < 16) ? scr[wid * 16 + lane] : 0.0;
#pragma unroll
        for (int o = 8; o; o >>= 1) u += __shfl_down_sync(0xFFFFFFFFu, u, o);
        if (lane == 0) scr[36 + wid] = u;
    }
    __syncthreads();
    a = scr[36];
    b = scr[37];
}
__device__ __forceinline__ void bredd5(double v[5], double* scr, int tid) {
    int lane = tid & 31, wid = tid >> 5;
#pragma unroll
    for (int k = 0; k < 5; k++) v[k] = warp_red_d(v[k]);
    if (lane == 0) {
#pragma unroll
        for (int k = 0; k < 5; k++) scr[((k < 2) ? k : (k + 0)) * 0 + k] = 0.0; // no-op guard
    }
    __syncthreads();
    // simple: two-stage via scr layout [k*8+wid/2]? keep original proven layout:
    if (lane == 0) {
#pragma unroll
        for (int k = 0; k < 5; k++) scr[k * 16 + wid] = v[k];
    }
    __syncthreads();
    if (wid < 5) {
        double u = (lane < 16) ? scr[wid * 16 + lane] : 0.0;
#pragma unroll
        for (int o = 8; o; o >>= 1) u += __shfl_down_sync(0xFFFFFFFFu, u, o);
        if (lane == 0) scr[80 + wid] = u;
    }
    __syncthreads();
#pragma unroll
    for (int k = 0; k < 5; k++) v[k] = scr[80 + k];
}
// single-barrier fp32 block reduction (16 warps)
__device__ __forceinline__ float bred1(float v, float* scr, int tid) {
    const int lane = tid & 31, wid = tid >> 5;
#pragma unroll
    for (int o = 16; o; o >>= 1) v += __shfl_xor_sync(0xFFFFFFFFu, v, o);
    if (lane == 0) scr[wid] = v;
    __syncthreads();
    float u = scr[lane & 15];
#pragma unroll
    for (int o = 8; o; o >>= 1) u += __shfl_xor_sync(0xFFFFFFFFu, u, o);
    return u;
}

#define GATHF(arr, q0, q1, q2)                                                \
    ( *(const float*)((const char*)(arr) + ((q0) & 0xFFFFu))                  \
    + *(const float*)((const char*)(arr) + ((q0) >> 16))                      \
    + *(const float*)((const char*)(arr) + ((q1) & 0xFFFFu))                  \
    + *(const float*)((const char*)(arr) + ((q1) >> 16))                      \
    + *(const float*)((const char*)(arr) + ((q2) & 0xFFFFu))                  \
    + *(const float*)((const char*)(arr) + ((q2) >> 16)) )
#define GATHD(arr, q0, q1, q2)                                                \
    ( *(const double*)((const char*)(arr) + (((q0) & 0xFFFFu) << 1))          \
    + *(const double*)((const char*)(arr) + (((q0) >> 16)     << 1))          \
    + *(const double*)((const char*)(arr) + (((q1) & 0xFFFFu) << 1))          \
    + *(const double*)((const char*)(arr) + (((q1) >> 16)     << 1))          \
    + *(const double*)((const char*)(arr) + (((q2) & 0xFFFFu) << 1))          \
    + *(const double*)((const char*)(arr) + (((q2) >> 16)     << 1)) )

// one Richardson step: publish r, barrier, dx += r, r = N r
#define RICH_STEP(BUF)                                                        \
    do {                                                                      \
        _Pragma("unroll")                                                     \
        for (int t = 0; t < RPT; t++) (BUF)[tid + t * NT] = rg[t];            \
        __syncthreads();                                                      \
        _Pragma("unroll")                                                     \
        for (int t = 0; t < RPT; t++) {                                       \
            const float sum = GATHF((BUF), pk[t][0], pk[t][1], pk[t][2]);     \
            dx[t] += rg[t];                                                   \
            rg[t] = wf[t] * sum;                                              \
        }                                                                     \
    } while (0)

__global__ __launch_bounds__(NT, 1)
void solve_kernel(const float* __restrict__ th1,
                  const float* __restrict__ th2,
                  const float* __restrict__ th3,
                  const float* __restrict__ cd,
                  const float* __restrict__ Iexp,
                  const int*   __restrict__ nbr,
                  float*       __restrict__ out)
{
    extern __shared__ double sm[];
    double* xd   = sm;                 // 4097 (pad slot 4096 == 0)
    double* vd   = sm + 4097;          // 4097 (pad slot 4096 == 0) — fp64 staging
    double* wdm  = sm + 8194;          // 4096 fp64 Jacobi weight
    double* bhdm = sm + 12290;         // 4096 fp64 hatted RHS
    double* scrd = sm + 16386;         // 40
    float*  fb   = (float*)(sm + 16426);
    float* pf   = fb;                  // 4097 (pad 0)
    float* sf   = fb + 4097;           // 4097 (pad 0)
    float* scrf = fb + 8194;           // 32
    __shared__ int s_last;

    const int tid = threadIdx.x;
    const int sys = blockIdx.x;
    const float* th = (sys == 0) ? th1 : ((sys == 1) ? th2 : th3);

    const double L_C     = 8.45e-05;
    const double L_RATIO = 1.0 / sqrt(3.0);
    const double AREA    = sqrt(3.0) * 0.5 * L_C * L_C;
    const double A_SCALE = 1.0e11;
    const double B_SCALE = 1.0e23;

    const double D   = (double)th[0];
    const double lam = (double)th[1];
    const double K   = (double)th[7];
    double rho_p[NCELL], rec[NCELL], recK[NCELL];
#pragma unroll
    for (int c = 0; c < NCELL; c++) {
        rho_p[c] = (double)th[2 + c];
        rec[c]   = (double)th[8 + c];
        recK[c]  = rec[c] * K;
    }
    const double Dp = D * L_RATIO;

    uint32_t pk[RPT][3];               // packed byte offsets (idx*4), pad = 4096*4
    float wf[RPT];
    float rg[RPT], dx[RPT], vr[RPT], ug[RPT];

    // ---- setup ----
    double bb_part = 0.0;
#pragma unroll
    for (int t = 0; t < RPT; t++) {
        const int i = tid + t * NT;
        int nb[6];
#pragma unroll
        for (int j = 0; j < 6; j++) nb[j] = nbr[i * 6 + j];
#pragma unroll
        for (int j = 1; j < 6; j++)
#pragma unroll
            for (int l = 0; l < 6; l++)
                if (l < j && nb[j] == nb[l]) nb[j] = NROW;   // dup -> pad slot
        pk[t][0] = ((uint32_t)nb[0] * 4u) | (((uint32_t)nb[1] * 4u) << 16);
        pk[t][1] = ((uint32_t)nb[2] * 4u) | (((uint32_t)nb[3] * 4u) << 16);
        pk[t][2] = ((uint32_t)nb[4] * 4u) | (((uint32_t)nb[5] * 4u) << 16);

        double drec = 0.0, drho = 0.0;
#pragma unroll
        for (int c = 0; c < NCELL; c++) {
            const double f = (double)cd[i * NCELL + c];
            drec += f * recK[c];
            drho += f * rho_p[c];
        }
        const double diag = 6.0 * Dp + AREA * (lam + drec);
        const double wdv  = Dp / diag;
        const double bh   = AREA * drho * B_SCALE / (A_SCALE * diag);
        wdm[i]  = wdv;
        bhdm[i] = bh;
        wf[t]   = (float)wdv;
        rg[t]   = (float)bh;
        dx[t]   = 0.0f;
        xd[i]   = 0.0;
        bb_part += bh * bh;
    }
    if (tid == 0) { pf[NROW] = 0.0f; sf[NROW] = 0.0f; xd[NROW] = 0.0; vd[NROW] = 0.0; }
    __syncthreads();

    const double bb   = blk_red_d(bb_part, scrd, tid);
    const double tolo = bb * 9e-10;    // outer relres 3e-5

    // ---- pass 1a: 14 Richardson steps (r becomes Perron estimate) ----
#pragma unroll 1
    for (int k = 0; k < NEUM1A; k++) {
        float* buf = (k & 1) ? sf : pf;
        RICH_STEP(buf);
    }

    // ---- build deflation pair from r: v = r ; u = (I - N) v in fp64 ----
#pragma unroll
    for (int t = 0; t < RPT; t++) {
        vr[t] = rg[t];
        vd[tid + t * NT] = (double)rg[t];
    }
    __syncthreads();
    double uu = 0.0, uv = 0.0;
#pragma unroll
    for (int t = 0; t < RPT; t++) {
        const int i = tid + t * NT;
        const double sum = GATHD(vd, pk[t][0], pk[t][1], pk[t][2]);
        const double ud  = (double)vr[t] - wdm[i] * sum;
        ug[t] = (float)ud;
        uu += ud * ud;
        uv += ud * (double)vr[t];
    }
    bredd2(uu, uv, scrd, tid);
    const float inv_uu = (uu > 0.0) ? (float)(1.0 / uu) : 0.0f;

    // ---- first deflation (exact fp64 coefficient) ----
    {
        const double Cd = (uu > 0.0) ? (uv / uu) : 0.0;
        const float  c  = (float)Cd;
#pragma unroll
        for (int t = 0; t < RPT; t++) rg[t] = fmaf(-c, ug[t], rg[t]);

        // ---- pass 1b: 5 more steps on the (bulk) leftover ----
#pragma unroll 1
        for (int k = 0; k < NEUM1B; k++) {
            float* buf = (k & 1) ? sf : pf;
            RICH_STEP(buf);
        }

        // ---- fold + fp64 true residual ----
#pragma unroll
        for (int t = 0; t < RPT; t++) {
            xd[tid + t * NT] += (double)dx[t] + Cd * (double)vr[t];
            dx[t] = 0.0f;
        }
        __syncthreads();
    }
    double rn2d;
    {
        double rp = 0.0;
#pragma unroll
        for (int t = 0; t < RPT; t++) {
            const int i = tid + t * NT;
            const double sum = GATHD(xd, pk[t][0], pk[t][1], pk[t][2]);
            const double rdi = bhdm[i] - (xd[i] - wdm[i] * sum);
            rg[t] = (float)rdi;
            rp += rdi * rdi;
        }
        rn2d = blk_red_d(rp, scrd, tid);
    }

    // ---- safety passes: reuse (v, u) ----
#pragma unroll 1
    for (int outer = 1; outer < MAX_OUTER && rn2d > tolo; outer++) {
        float up = 0.0f;
#pragma unroll
        for (int t = 0; t < RPT; t++) up = fmaf(ug[t], rg[t], up);
        up = bred1(up, scrf, tid);
        const float  c  = up * inv_uu;
        const double Cd = (double)c;
#pragma unroll
        for (int t = 0; t < RPT; t++) rg[t] = fmaf(-c, ug[t], rg[t]);

#pragma unroll 1
        for (int k = 0; k < NEUM2; k++) {
            float* buf = (k & 1) ? sf : pf;
            RICH_STEP(buf);
        }

#pragma unroll
        for (int t = 0; t < RPT; t++) {
            xd[tid + t * NT] += (double)dx[t] + Cd * (double)vr[t];
            dx[t] = 0.0f;
        }
        __syncthreads();
        double rp = 0.0;
#pragma unroll
        for (int t = 0; t < RPT; t++) {
            const int i = tid + t * NT;
            const double sum = GATHD(xd, pk[t][0], pk[t][1], pk[t][2]);
            const double rdi = bhdm[i] - (xd[i] - wdm[i] * sum);
            rg[t] = (float)rdi;
            rp += rdi * rdi;
        }
        rn2d = blk_red_d(rp, scrd, tid);
    }

    // ---- epilogue (fp64) ----
    double part[NCELL] = {0, 0, 0, 0, 0};
#pragma unroll
    for (int t = 0; t < RPT; t++) {
        const int i = tid + t * NT;
        double num[NCELL], den = 0.0;
#pragma unroll
        for (int c = 0; c < NCELL; c++) {
            num[c] = (double)cd[i * NCELL + c] * rho_p[c];
            den += num[c];
        }
        const double gi = xd[i] / den;
#pragma unroll
        for (int c = 0; c < NCELL; c++) part[c] += gi * num[c];
    }
    bredd5(part, scrd, tid);

    if (tid < 25) {
        const int a = tid / 5, c = tid % 5;
        g_IM[sys * 25 + tid] = K * rec[a] * part[c] / (double)NROW;
        __threadfence();
    }
    __syncthreads();

    // ---- last block computes the loss ----
    if (tid == 0) {
        __threadfence();
        s_last = (atomicAdd(&g_cnt, 1) == 2) ? 1 : 0;
    }
    __syncthreads();
    if (s_last && tid < 32) {
        __threadfence();
        double s_m = 0, s_d = 0, s_mm = 0, s_dd = 0, s_md = 0;
        for (int i = tid; i < 75; i += 32) {
            const double m = *((volatile double*)&g_IM[i]);
            const double d = (double)Iexp[i];
            s_m += m; s_d += d; s_mm += m * m; s_dd += d * d; s_md += m * d;
        }
        s_m  = warp_red_d(s_m);
        s_d  = warp_red_d(s_d);
        s_mm = warp_red_d(s_mm);
        s_dd = warp_red_d(s_dd);
        s_md = warp_red_d(s_md);
        if (tid == 0) {
            const double n  = 75.0;
            const double mm = s_m / n, md = s_d / n;
            const double cov = s_md / n - mm * md;
            const double vm  = s_mm / n - mm * mm;
            const double vd2 = s_dd / n - md * md;
            out[0] = (float)(1.0 - cov / (sqrt(vm) * sqrt(vd2)));
            atomicExch(&g_cnt, 0);
        }
    }
}

extern "C" void kernel_launch(void* const* d_in, const int* in_sizes, int n_in,
                              void* d_out, int out_size)
{
    const float* th1  = (const float*)d_in[0];
    const float* th2  = (const float*)d_in[1];
    const float* th3  = (const float*)d_in[2];
    const float* cd   = (const float*)d_in[3];
    const float* Iexp = (const float*)d_in[4];
    const int*   nbr  = (const int*)d_in[5];

    cudaFuncSetAttribute(solve_kernel,
                         cudaFuncAttributeMaxDynamicSharedMemorySize, SM_BYTES);

    solve_kernel<<<3, NT, SM_BYTES>>>(th1, th2, th3, cd, Iexp, nbr, (float*)d_out);
}

// round 16
// speedup vs baseline: 1.4731x; 1.0596x over previous
#include <cuda_runtime.h>
#include <math.h>
#include <stdint.h>

#define NROW      4096
#define NT        512
#define RPT       8
#define NCELL     5
#define NEUM1A    14     // Richardson steps before deflation (r -> Perron estimate)
#define NEUM1B    7      // steps after first deflation (leftover 4e-3 * 0.41^7 ~ 8e-6)
#define NEUM2     6      // steps in safety passes (guard only)
#define MAX_OUTER 3

// smem doubles: xd[4097] vd[4097] wdm[4096] bhdm[4096] scrd[40]
// smem floats:  pf[4097] sf[4097] scrf[32]
#define SM_DBL  (4097 + 4097 + 4096 + 4096 + 40)
#define SM_BYTES (SM_DBL * 8 + (4097 + 4097 + 32) * 4)

__device__ double g_IM[75];
__device__ int    g_cnt = 0;

__device__ __forceinline__ double warp_red_d(double v) {
#pragma unroll
    for (int o = 16; o; o >>= 1) v += __shfl_down_sync(0xFFFFFFFFu, v, o);
    return v;
}
__device__ __forceinline__ double blk_red_d(double v, double* scr, int tid) {
    int lane = tid & 31, wid = tid >> 5;
    v = warp_red_d(v);
    if (lane == 0) scr[wid] = v;
    __syncthreads();
    if (wid == 0) {
        double u = (lane < 16) ? scr[lane] : 0.0;
#pragma unroll
        for (int o = 8; o; o >>= 1) u += __shfl_down_sync(0xFFFFFFFFu, u, o);
        if (lane == 0) scr[32] = u;
    }
    __syncthreads();
    return scr[32];
}
// fused 2-way fp64 block reduction
__device__ __forceinline__ void bredd2(double& a, double& b, double* scr, int tid) {
    int lane = tid & 31, wid = tid >> 5;
    a = warp_red_d(a);
    b = warp_red_d(b);
    if (lane == 0) { scr[wid] = a; scr[16 + wid] = b; }
    __syncthreads();
    if (wid < 2) {
        double u = (lane < 16) ? scr[wid * 16 + lane] : 0.0;
#pragma unroll
        for (int o = 8; o; o >>= 1) u += __shfl_down_sync(0xFFFFFFFFu, u, o);
        if (lane == 0) scr[36 + wid] = u;
    }
    __syncthreads();
    a = scr[36];
    b = scr[37];
}
__device__ __forceinline__ void bredd5(double v[5], double* scr, int tid) {
    int lane = tid & 31, wid = tid >> 5;
#pragma unroll
    for (int k = 0; k < 5; k++) v[k] = warp_red_d(v[k]);
    if (lane == 0) {
#pragma unroll
        for (int k = 0; k < 5; k++) scr[k * 16 + wid] = v[k];
    }
    __syncthreads();
    if (wid < 5) {
        double u = (lane < 16) ? scr[wid * 16 + lane] : 0.0;
#pragma unroll
        for (int o = 8; o; o >>= 1) u += __shfl_down_sync(0xFFFFFFFFu, u, o);
        if (lane == 0) scr[80 + wid] = u;
    }
    __syncthreads();
#pragma unroll
    for (int k = 0; k < 5; k++) v[k] = scr[80 + k];
}
// single-barrier fp32 block reduction (16 warps)
__device__ __forceinline__ float bred1(float v, float* scr, int tid) {
    const int lane = tid & 31, wid = tid >> 5;
#pragma unroll
    for (int o = 16; o; o >>= 1) v += __shfl_xor_sync(0xFFFFFFFFu, v, o);
    if (lane == 0) scr[wid] = v;
    __syncthreads();
    float u = scr[lane & 15];
#pragma unroll
    for (int o = 8; o; o >>= 1) u += __shfl_xor_sync(0xFFFFFFFFu, u, o);
    return u;
}

#define GATHF(arr, q0, q1, q2)                                                \
    ( *(const float*)((const char*)(arr) + ((q0) & 0xFFFFu))                  \
    + *(const float*)((const char*)(arr) + ((q0) >> 16))                      \
    + *(const float*)((const char*)(arr) + ((q1) & 0xFFFFu))                  \
    + *(const float*)((const char*)(arr) + ((q1) >> 16))                      \
    + *(const float*)((const char*)(arr) + ((q2) & 0xFFFFu))                  \
    + *(const float*)((const char*)(arr) + ((q2) >> 16)) )
#define GATHD(arr, q0, q1, q2)                                                \
    ( *(const double*)((const char*)(arr) + (((q0) & 0xFFFFu) << 1))          \
    + *(const double*)((const char*)(arr) + (((q0) >> 16)     << 1))          \
    + *(const double*)((const char*)(arr) + (((q1) & 0xFFFFu) << 1))          \
    + *(const double*)((const char*)(arr) + (((q1) >> 16)     << 1))          \
    + *(const double*)((const char*)(arr) + (((q2) & 0xFFFFu) << 1))          \
    + *(const double*)((const char*)(arr) + (((q2) >> 16)     << 1)) )

// one Richardson step: publish r, barrier, dx += r, r = N r
#define RICH_STEP(BUF)                                                        \
    do {                                                                      \
        _Pragma("unroll")                                                     \
        for (int t = 0; t < RPT; t++) (BUF)[tid + t * NT] = rg[t];            \
        __syncthreads();                                                      \
        _Pragma("unroll")                                                     \
        for (int t = 0; t < RPT; t++) {                                       \
            const float sum = GATHF((BUF), pk[t][0], pk[t][1], pk[t][2]);     \
            dx[t] += rg[t];                                                   \
            rg[t] = wf[t] * sum;                                              \
        }                                                                     \
    } while (0)

__global__ __launch_bounds__(NT, 1)
void solve_kernel(const float* __restrict__ th1,
                  const float* __restrict__ th2,
                  const float* __restrict__ th3,
                  const float* __restrict__ cd,
                  const float* __restrict__ Iexp,
                  const int*   __restrict__ nbr,
                  float*       __restrict__ out)
{
    extern __shared__ double sm[];
    double* xd   = sm;                 // 4097 (pad slot 4096 == 0)
    double* vd   = sm + 4097;          // 4097 (pad slot 4096 == 0)
    double* wdm  = sm + 8194;          // 4096 fp64 Jacobi weight
    double* bhdm = sm + 12290;         // 4096 fp64 hatted RHS
    double* scrd = sm + 16386;         // 40
    float*  fb   = (float*)(sm + 16426);
    float* pf   = fb;                  // 4097 (pad 0)
    float* sf   = fb + 4097;           // 4097 (pad 0)
    float* scrf = fb + 8194;           // 32
    __shared__ int s_last;

    const int tid = threadIdx.x;
    const int sys = blockIdx.x;
    const float* th = (sys == 0) ? th1 : ((sys == 1) ? th2 : th3);

    const double L_C     = 8.45e-05;
    const double L_RATIO = 1.0 / sqrt(3.0);
    const double AREA    = sqrt(3.0) * 0.5 * L_C * L_C;
    const double A_SCALE = 1.0e11;
    const double B_SCALE = 1.0e23;

    const double D   = (double)th[0];
    const double lam = (double)th[1];
    const double K   = (double)th[7];
    double rho_p[NCELL], rec[NCELL], recK[NCELL];
#pragma unroll
    for (int c = 0; c < NCELL; c++) {
        rho_p[c] = (double)th[2 + c];
        rec[c]   = (double)th[8 + c];
        recK[c]  = rec[c] * K;
    }
    const double Dp = D * L_RATIO;
    const double BA = B_SCALE / A_SCALE;

    uint32_t pk[RPT][3];               // packed byte offsets (idx*4), pad = 4096*4
    float wf[RPT];
    float rg[RPT], dx[RPT], vr[RPT], ug[RPT];

    // ---- setup ----
    double bb_part = 0.0;
#pragma unroll
    for (int t = 0; t < RPT; t++) {
        const int i = tid + t * NT;
        int nb[6];
#pragma unroll
        for (int j = 0; j < 6; j++) nb[j] = nbr[i * 6 + j];
#pragma unroll
        for (int j = 1; j < 6; j++)
#pragma unroll
            for (int l = 0; l < 6; l++)
                if (l < j && nb[j] == nb[l]) nb[j] = NROW;   // dup -> pad slot
        pk[t][0] = ((uint32_t)nb[0] * 4u) | (((uint32_t)nb[1] * 4u) << 16);
        pk[t][1] = ((uint32_t)nb[2] * 4u) | (((uint32_t)nb[3] * 4u) << 16);
        pk[t][2] = ((uint32_t)nb[4] * 4u) | (((uint32_t)nb[5] * 4u) << 16);

        double drec = 0.0, drho = 0.0;
#pragma unroll
        for (int c = 0; c < NCELL; c++) {
            const double f = (double)cd[i * NCELL + c];
            drec += f * recK[c];
            drho += f * rho_p[c];
        }
        const double diag = 6.0 * Dp + AREA * (lam + drec);
        const double inv  = 1.0 / diag;            // single fp64 divide
        const double wdv  = Dp * inv;
        const double bh   = AREA * drho * BA * inv;
        wdm[i]  = wdv;
        bhdm[i] = bh;
        wf[t]   = (float)wdv;
        rg[t]   = (float)bh;
        dx[t]   = 0.0f;
        xd[i]   = 0.0;
        bb_part += bh * bh;
    }
    if (tid == 0) { pf[NROW] = 0.0f; sf[NROW] = 0.0f; xd[NROW] = 0.0; vd[NROW] = 0.0; }
    __syncthreads();

    const double bb   = blk_red_d(bb_part, scrd, tid);
    const double tolo = bb * 9e-10;    // outer relres 3e-5

    // ---- pass 1a: 14 Richardson steps (r becomes Perron estimate) ----
#pragma unroll 1
    for (int k = 0; k < NEUM1A; k++) {
        float* buf = (k & 1) ? sf : pf;
        RICH_STEP(buf);
    }

    // ---- build deflation pair from r: v = r ; u = (I - N) v in fp64 ----
#pragma unroll
    for (int t = 0; t < RPT; t++) {
        vr[t] = rg[t];
        vd[tid + t * NT] = (double)rg[t];
    }
    __syncthreads();
    double uu = 0.0, uv = 0.0;
#pragma unroll
    for (int t = 0; t < RPT; t++) {
        const int i = tid + t * NT;
        const double sum = GATHD(vd, pk[t][0], pk[t][1], pk[t][2]);
        const double ud  = (double)vr[t] - wdm[i] * sum;
        ug[t] = (float)ud;
        uu += ud * ud;
        uv += ud * (double)vr[t];
    }
    bredd2(uu, uv, scrd, tid);
    const float inv_uu = (uu > 0.0) ? (float)(1.0 / uu) : 0.0f;

    // ---- first deflation (exact fp64 coefficient) ----
    {
        const double Cd = (uu > 0.0) ? (uv / uu) : 0.0;
        const float  c  = (float)Cd;
#pragma unroll
        for (int t = 0; t < RPT; t++) rg[t] = fmaf(-c, ug[t], rg[t]);

        // ---- pass 1b: 7 more steps on the (bulk) leftover ----
#pragma unroll 1
        for (int k = 0; k < NEUM1B; k++) {
            float* buf = (k & 1) ? sf : pf;
            RICH_STEP(buf);
        }

        // ---- fold + fp64 true residual ----
#pragma unroll
        for (int t = 0; t < RPT; t++) {
            xd[tid + t * NT] += (double)dx[t] + Cd * (double)vr[t];
            dx[t] = 0.0f;
        }
        __syncthreads();
    }
    double rn2d;
    {
        double rp = 0.0;
#pragma unroll
        for (int t = 0; t < RPT; t++) {
            const int i = tid + t * NT;
            const double sum = GATHD(xd, pk[t][0], pk[t][1], pk[t][2]);
            const double rdi = bhdm[i] - (xd[i] - wdm[i] * sum);
            rg[t] = (float)rdi;
            rp += rdi * rdi;
        }
        rn2d = blk_red_d(rp, scrd, tid);
    }

    // ---- safety passes (guard; expected skipped): reuse (v, u) ----
#pragma unroll 1
    for (int outer = 1; outer < MAX_OUTER && rn2d > tolo; outer++) {
        float up = 0.0f;
#pragma unroll
        for (int t = 0; t < RPT; t++) up = fmaf(ug[t], rg[t], up);
        up = bred1(up, scrf, tid);
        const float  c  = up * inv_uu;
        const double Cd = (double)c;
#pragma unroll
        for (int t = 0; t < RPT; t++) rg[t] = fmaf(-c, ug[t], rg[t]);

#pragma unroll 1
        for (int k = 0; k < NEUM2; k++) {
            float* buf = (k & 1) ? sf : pf;
            RICH_STEP(buf);
        }

#pragma unroll
        for (int t = 0; t < RPT; t++) {
            xd[tid + t * NT] += (double)dx[t] + Cd * (double)vr[t];
            dx[t] = 0.0f;
        }
        __syncthreads();
        double rp = 0.0;
#pragma unroll
        for (int t = 0; t < RPT; t++) {
            const int i = tid + t * NT;
            const double sum = GATHD(xd, pk[t][0], pk[t][1], pk[t][2]);
            const double rdi = bhdm[i] - (xd[i] - wdm[i] * sum);
            rg[t] = (float)rdi;
            rp += rdi * rdi;
        }
        rn2d = blk_red_d(rp, scrd, tid);
    }

    // ---- epilogue (fp64) ----
    double part[NCELL] = {0, 0, 0, 0, 0};
#pragma unroll
    for (int t = 0; t < RPT; t++) {
        const int i = tid + t * NT;
        double num[NCELL], den = 0.0;
#pragma unroll
        for (int c = 0; c < NCELL; c++) {
            num[c] = (double)cd[i * NCELL + c] * rho_p[c];
            den += num[c];
        }
        const double gi = xd[i] / den;
#pragma unroll
        for (int c = 0; c < NCELL; c++) part[c] += gi * num[c];
    }
    bredd5(part, scrd, tid);

    if (tid < 25) {
        const int a = tid / 5, c = tid % 5;
        g_IM[sys * 25 + tid] = K * rec[a] * part[c] / (double)NROW;
        __threadfence();
    }
    __syncthreads();

    // ---- last block computes the loss ----
    if (tid == 0) {
        __threadfence();
        s_last = (atomicAdd(&g_cnt, 1) == 2) ? 1 : 0;
    }
    __syncthreads();
    if (s_last && tid < 32) {
        __threadfence();
        double s_m = 0, s_d = 0, s_mm = 0, s_dd = 0, s_md = 0;
        for (int i = tid; i < 75; i += 32) {
            const double m = *((volatile double*)&g_IM[i]);
            const double d = (double)Iexp[i];
            s_m += m; s_d += d; s_mm += m * m; s_dd += d * d; s_md += m * d;
        }
        s_m  = warp_red_d(s_m);
        s_d  = warp_red_d(s_d);
        s_mm = warp_red_d(s_mm);
        s_dd = warp_red_d(s_dd);
        s_md = warp_red_d(s_md);
        if (tid == 0) {
            const double n  = 75.0;
            const double mm = s_m / n, md = s_d / n;
            const double cov = s_md / n - mm * md;
            const double vm  = s_mm / n - mm * mm;
            const double vd2 = s_dd / n - md * md;
            out[0] = (float)(1.0 - cov / (sqrt(vm) * sqrt(vd2)));
            atomicExch(&g_cnt, 0);
        }
    }
}

extern "C" void kernel_launch(void* const* d_in, const int* in_sizes, int n_in,
                              void* d_out, int out_size)
{
    const float* th1  = (const float*)d_in[0];
    const float* th2  = (const float*)d_in[1];
    const float* th3  = (const float*)d_in[2];
    const float* cd   = (const float*)d_in[3];
    const float* Iexp = (const float*)d_in[4];
    const int*   nbr  = (const int*)d_in[5];

    cudaFuncSetAttribute(solve_kernel,
                         cudaFuncAttributeMaxDynamicSharedMemorySize, SM_BYTES);

    solve_kernel<<<3, NT, SM_BYTES>>>(th1, th2, th3, cd, Iexp, nbr, (float*)d_out);
}